// round 3
// baseline (speedup 1.0000x reference)
#include <cuda_runtime.h>
#include <cstdint>

#define NUM_NODE 50000
#define NUM_EDGE 1600000
#define NUM_REL  512
#define DIM      64

// Scratch accumulators (alloc-free rule: __device__ globals)
__device__ float g_s[NUM_NODE * DIM];
__device__ float g_sq[NUM_NODE * DIM];
__device__ float g_deg[NUM_NODE];

// ---------------------------------------------------------------------------
// K0: init s = boundary, sq = boundary^2, deg = 0
// ---------------------------------------------------------------------------
__global__ void init_kernel(const float* __restrict__ boundary) {
    int i = blockIdx.x * blockDim.x + threadIdx.x;
    if (i < NUM_NODE * DIM) {
        float b = boundary[i];
        g_s[i]  = b;
        g_sq[i] = b * b;
    }
    if (i < NUM_NODE) g_deg[i] = 0.0f;
}

// ---------------------------------------------------------------------------
// K1: per-edge gather-multiply + vectorized scatter-add
// 16 lanes per edge (each lane owns a float4 of the 64-dim row),
// 2 edges per warp, 16 edges per 256-thread block.
// ---------------------------------------------------------------------------
__global__ void __launch_bounds__(256) edge_kernel(
    const float* __restrict__ input,
    const int*   __restrict__ edge_list,
    const float* __restrict__ edge_weight,
    const float* __restrict__ relw)
{
    int warp_global = (blockIdx.x * blockDim.x + threadIdx.x) >> 5;
    int lane = threadIdx.x & 31;
    int g    = lane >> 4;    // which edge in this warp (0/1)
    int sub  = lane & 15;    // float4 index within the 64-dim row

    long e = (long)warp_global * 2 + g;
    if (e >= NUM_EDGE) return;

    int   u = __ldg(&edge_list[e * 3 + 0]);
    int   v = __ldg(&edge_list[e * 3 + 1]);
    int   r = __ldg(&edge_list[e * 3 + 2]);
    float w = __ldg(&edge_weight[e]);

    const float4* xin = (const float4*)(input + (size_t)u * DIM) + sub;
    const float4* rin = (const float4*)(relw  + (size_t)r * DIM) + sub;
    float4 x  = __ldg(xin);
    float4 rr = __ldg(rin);

    float4 m;
    m.x = x.x * rr.x * w;
    m.y = x.y * rr.y * w;
    m.z = x.z * rr.z * w;
    m.w = x.w * rr.w * w;

    float4 m2;
    m2.x = m.x * m.x;
    m2.y = m.y * m.y;
    m2.z = m.z * m.z;
    m2.w = m.w * m.w;

    float* sp  = g_s  + (size_t)v * DIM + sub * 4;
    float* sqp = g_sq + (size_t)v * DIM + sub * 4;

    asm volatile("red.global.add.v4.f32 [%0], {%1, %2, %3, %4};"
                 :: "l"(sp), "f"(m.x), "f"(m.y), "f"(m.z), "f"(m.w)
                 : "memory");
    asm volatile("red.global.add.v4.f32 [%0], {%1, %2, %3, %4};"
                 :: "l"(sqp), "f"(m2.x), "f"(m2.y), "f"(m2.z), "f"(m2.w)
                 : "memory");

    if (sub == 0) atomicAdd(&g_deg[v], 1.0f);
}

// ---------------------------------------------------------------------------
// K2: per-node variance update + 64x64 GEMM epilogue
// Block = 256 threads, tile of 64 nodes.
// Each thread owns (node = tid>>2, 16 output columns = (tid&3)*16 ..).
// ---------------------------------------------------------------------------
__global__ void __launch_bounds__(256) update_gemm_kernel(
    const float* __restrict__ W,
    const float* __restrict__ b,
    float* __restrict__ out)
{
    __shared__ float Wsh[DIM * DIM];   // Wsh[d*64 + j] = W[j*64 + d]
    __shared__ float Ush[64 * (DIM + 1)];  // padded stride 65 to avoid conflicts
    __shared__ float bsh[DIM];

    int tid = threadIdx.x;

    // Load W transposed into shared
    for (int i = tid; i < DIM * DIM; i += 256) {
        int j = i >> 6, d = i & 63;
        Wsh[d * DIM + j] = W[i];
    }
    if (tid < DIM) bsh[tid] = b[tid];

    int n0 = blockIdx.x * 64;

    // Compute u for the 64-node tile (coalesced reads of s, sq)
    for (int i = tid; i < 64 * DIM; i += 256) {
        int nl = i >> 6, d = i & 63;
        int n  = n0 + nl;
        float s = 0.f, sq = 0.f, dg = 0.f;
        if (n < NUM_NODE) {
            s  = g_s[(size_t)n0 * DIM + i];
            sq = g_sq[(size_t)n0 * DIM + i];
            dg = g_deg[n];
        }
        float inv = 1.0f / (dg + 1.0f);
        float sm  = s * inv;
        float var = sq * inv - sm * sm;
        Ush[nl * (DIM + 1) + d] = sqrtf(fmaxf(var, 1e-6f));
    }
    __syncthreads();

    int nl = tid >> 2;
    int j0 = (tid & 3) * 16;

    float acc[16];
    #pragma unroll
    for (int k = 0; k < 16; k++) acc[k] = bsh[j0 + k];

    #pragma unroll 4
    for (int d = 0; d < DIM; d++) {
        float u = Ush[nl * (DIM + 1) + d];
        const float4* wrow = (const float4*)&Wsh[d * DIM + j0];
        float4 w0 = wrow[0];
        float4 w1 = wrow[1];
        float4 w2 = wrow[2];
        float4 w3 = wrow[3];
        acc[0]  += u * w0.x;  acc[1]  += u * w0.y;
        acc[2]  += u * w0.z;  acc[3]  += u * w0.w;
        acc[4]  += u * w1.x;  acc[5]  += u * w1.y;
        acc[6]  += u * w1.z;  acc[7]  += u * w1.w;
        acc[8]  += u * w2.x;  acc[9]  += u * w2.y;
        acc[10] += u * w2.z;  acc[11] += u * w2.w;
        acc[12] += u * w3.x;  acc[13] += u * w3.y;
        acc[14] += u * w3.z;  acc[15] += u * w3.w;
    }

    int n = n0 + nl;
    if (n < NUM_NODE) {
        float4* op = (float4*)(out + (size_t)n * DIM + j0);
        op[0] = make_float4(acc[0],  acc[1],  acc[2],  acc[3]);
        op[1] = make_float4(acc[4],  acc[5],  acc[6],  acc[7]);
        op[2] = make_float4(acc[8],  acc[9],  acc[10], acc[11]);
        op[3] = make_float4(acc[12], acc[13], acc[14], acc[15]);
    }
}

// ---------------------------------------------------------------------------
// Launch
// Inputs (metadata order): input, boundary, edge_list, edge_weight,
//                          relation_weight, W, b
// ---------------------------------------------------------------------------
extern "C" void kernel_launch(void* const* d_in, const int* in_sizes, int n_in,
                              void* d_out, int out_size)
{
    const float* input    = (const float*)d_in[0];
    const float* boundary = (const float*)d_in[1];
    const int*   edges    = (const int*)  d_in[2];
    const float* eweight  = (const float*)d_in[3];
    const float* relw     = (const float*)d_in[4];
    const float* W        = (const float*)d_in[5];
    const float* b        = (const float*)d_in[6];
    float*       out      = (float*)d_out;

    // K0: init accumulators
    {
        int total = NUM_NODE * DIM;
        int blocks = (total + 255) / 256;
        init_kernel<<<blocks, 256>>>(boundary);
    }

    // K1: edge scatter (16 edges per 256-thread block)
    {
        int blocks = (NUM_EDGE + 15) / 16;
        edge_kernel<<<blocks, 256>>>(input, edges, eweight, relw);
    }

    // K2: update + GEMM
    {
        int blocks = (NUM_NODE + 63) / 64;
        update_gemm_kernel<<<blocks, 256>>>(W, b, out);
    }
}